// round 1
// baseline (speedup 1.0000x reference)
#include <cuda_runtime.h>
#include <cuda_bf16.h>
#include <math.h>

#define Bn 8
#define Dn 1024
#define Gn 32
#define Kn 64
#define NPn 1024
#define NT 64        // n-rows per CTA
#define GSPLIT 4
#define GPER (Gn / GSPLIT)   // 8

// Scratch (device globals; no allocation allowed)
__device__ float g_xzT[(size_t)Bn * Dn * NPn];     // 32 MB: z transposed [b][d][n]
__device__ float g_cw[Bn * Gn * Kn];               // folded coeff*mask*weight*valid
__device__ char  g_gvalid[Bn * Gn];
__device__ float g_partial[GSPLIT * Bn * NPn];

// ---------------------------------------------------------------------------
// Kernel 1: detect valid_mask storage width, build cw + gvalid
// ---------------------------------------------------------------------------
__global__ void cmask_kernel(const void* __restrict__ vm,
                             const float* __restrict__ w,
                             const int* __restrict__ gc)
{
    __shared__ int mode;         // 1 = 4-byte elements, 0 = 1-byte elements
    __shared__ float cf[Kn];
    int tid = threadIdx.x;

    if (tid == 0) {
        const unsigned int* u = (const unsigned int*)vm;
        int m4 = 1;
        for (int i = 0; i < 16; ++i) {
            unsigned int v = u[i];
            if (v != 0u && v != 1u && v != 0x3F800000u) m4 = 0;
        }
        mode = m4;
    }
    if (tid < Kn) {
        cf[tid] = (float)pow(1.0e6, (double)tid / 63.0);
    }
    __syncthreads();

    for (int i = tid; i < Bn * Gn * Kn; i += blockDim.x) {
        int b = i / (Gn * Kn);
        int g = (i / Kn) % Gn;
        int k = i % Kn;
        bool m;
        if (mode) m = (((const unsigned int*)vm)[i] != 0u);
        else      m = (((const unsigned char*)vm)[i] != 0);
        float wv = (g < gc[b]) ? w[b * Gn + g] : 0.0f;
        g_cw[i] = m ? cf[k] * wv : 0.0f;
    }
    for (int i = tid; i < Bn * Gn; i += blockDim.x) {
        int b = i / Gn, g = i % Gn;
        g_gvalid[i] = (g < gc[b]) ? 1 : 0;
    }
}

// ---------------------------------------------------------------------------
// Kernel 2: xzT[b][d][n] = x[b][n][d] - xopt[b][d]  (tiled transpose)
// ---------------------------------------------------------------------------
__global__ void zt_kernel(const float* __restrict__ x,
                          const float* __restrict__ xopt)
{
    __shared__ float t[32][33];
    int b  = blockIdx.z;
    int n0 = blockIdx.x * 32;
    int d0 = blockIdx.y * 32;
    int tx = threadIdx.x, ty = threadIdx.y;

    #pragma unroll
    for (int j = ty; j < 32; j += 8) {
        int n = n0 + j, d = d0 + tx;
        t[j][tx] = x[((size_t)b * NPn + n) * Dn + d] - xopt[b * Dn + d];
    }
    __syncthreads();
    #pragma unroll
    for (int j = ty; j < 32; j += 8) {
        int d = d0 + j, n = n0 + tx;
        g_xzT[((size_t)b * Dn + d) * NPn + n] = t[tx][j];
    }
}

// ---------------------------------------------------------------------------
// Kernel 3: main fitness kernel.
// Grid: (Bn * NPn/NT, GSPLIT), block 256.
// Each CTA: n-tile of 64 rows, GPER groups; writes one partial slice.
// Thread tile: 2 n x 8 l (16 fp32 accumulators).
//   nt = tid & 31  -> n pair (2*nt, 2*nt+1)
//   lt = tid >> 5  -> l range [lt*8, lt*8+8)   (lt constant within a warp ->
//                     R reads are warp-broadcast LDS.128, crossbar-cheap)
// ---------------------------------------------------------------------------
__global__ __launch_bounds__(256) void fitness_kernel(
    const float* __restrict__ R,
    const int*   __restrict__ gidx,
    float*       __restrict__ partial)
{
    __shared__ float Rs[Kn * Kn];       // 16 KB
    __shared__ float zs[Kn * NT];       // 16 KB, [k][n]
    __shared__ float cws[Kn];
    __shared__ int   idxs[Kn];
    __shared__ float fit_s[NT];

    int tid   = threadIdx.x;
    int b     = blockIdx.x >> 4;
    int n0    = (blockIdx.x & 15) * NT;
    int gbase = blockIdx.y * GPER;
    int nt    = tid & 31;
    int lt    = tid >> 5;

    for (int i = tid; i < Kn * Kn; i += 256) Rs[i] = R[i];
    if (tid < NT) fit_s[tid] = 0.0f;

    float fa0 = 0.0f, fa1 = 0.0f;
    __syncthreads();

    for (int g = gbase; g < gbase + GPER; ++g) {
        if (!g_gvalid[b * Gn + g]) break;   // valid groups are a prefix
        __syncthreads();                    // prior compute done before rewrite
        if (tid < Kn) {
            idxs[tid] = gidx[(b * Gn + g) * Kn + tid];
            cws[tid]  = g_cw[(b * Gn + g) * Kn + tid];
        }
        __syncthreads();

        // Coalesced gather: 64 columns of xzT, each 64 consecutive n (float4)
        #pragma unroll
        for (int p = 0; p < 4; ++p) {
            int k   = p * 16 + (tid >> 4);
            int col = idxs[k];
            const float4* src =
                (const float4*)&g_xzT[((size_t)(b * Dn + col)) * NPn + n0] + (tid & 15);
            *((float4*)&zs[k * NT] + (tid & 15)) = *src;
        }
        __syncthreads();

        float cw_r[8];
        #pragma unroll
        for (int j = 0; j < 8; ++j) cw_r[j] = cws[lt * 8 + j];

        float acc[16];
        #pragma unroll
        for (int i = 0; i < 16; ++i) acc[i] = 0.0f;

        #pragma unroll 8
        for (int k = 0; k < Kn; ++k) {
            float2 z2 = *(const float2*)&zs[k * NT + nt * 2];
            float4 r0 = *(const float4*)&Rs[k * Kn + lt * 8];
            float4 r1 = *(const float4*)&Rs[k * Kn + lt * 8 + 4];
            acc[0]  += z2.x * r0.x;  acc[1]  += z2.x * r0.y;
            acc[2]  += z2.x * r0.z;  acc[3]  += z2.x * r0.w;
            acc[4]  += z2.x * r1.x;  acc[5]  += z2.x * r1.y;
            acc[6]  += z2.x * r1.z;  acc[7]  += z2.x * r1.w;
            acc[8]  += z2.y * r0.x;  acc[9]  += z2.y * r0.y;
            acc[10] += z2.y * r0.z;  acc[11] += z2.y * r0.w;
            acc[12] += z2.y * r1.x;  acc[13] += z2.y * r1.y;
            acc[14] += z2.y * r1.z;  acc[15] += z2.y * r1.w;
        }

        float s0 = 0.0f, s1 = 0.0f;
        #pragma unroll
        for (int j = 0; j < 8; ++j) {
            s0 += cw_r[j] * acc[j] * acc[j];
            s1 += cw_r[j] * acc[8 + j] * acc[8 + j];
        }
        fa0 += s0;
        fa1 += s1;
    }

    // Reduce the 8 l-chunks (one per warp) per n via shared atomics (512 total)
    atomicAdd(&fit_s[nt * 2],     fa0);
    atomicAdd(&fit_s[nt * 2 + 1], fa1);
    __syncthreads();
    if (tid < NT) {
        partial[(size_t)blockIdx.y * (Bn * NPn) + b * NPn + n0 + tid] = fit_s[tid];
    }
}

// ---------------------------------------------------------------------------
// Kernel 4: sum the GSPLIT partials
// ---------------------------------------------------------------------------
__global__ void sum_kernel(float* __restrict__ out)
{
    int i = blockIdx.x * blockDim.x + threadIdx.x;
    if (i < Bn * NPn) {
        float s = 0.0f;
        #pragma unroll
        for (int p = 0; p < GSPLIT; ++p) s += g_partial[p * (Bn * NPn) + i];
        out[i] = s;
    }
}

// ---------------------------------------------------------------------------
// kernel_launch
// Inputs (metadata order): x, weights, xopt, R, group_indices, valid_mask,
//                          group_counts
// ---------------------------------------------------------------------------
extern "C" void kernel_launch(void* const* d_in, const int* in_sizes, int n_in,
                              void* d_out, int out_size)
{
    const float* x      = (const float*)d_in[0];
    const float* w      = (const float*)d_in[1];
    const float* xopt   = (const float*)d_in[2];
    const float* R      = (const float*)d_in[3];
    const int*   gidx   = (const int*)d_in[4];
    const void*  vmask  = (const void*)d_in[5];
    const int*   gc     = (const int*)d_in[6];
    float*       out    = (float*)d_out;

    float* partial;
    cudaGetSymbolAddress((void**)&partial, g_partial);

    cmask_kernel<<<1, 256>>>(vmask, w, gc);

    dim3 tg(NPn / 32, Dn / 32, Bn);
    zt_kernel<<<tg, dim3(32, 8)>>>(x, xopt);

    dim3 fg(Bn * (NPn / NT), GSPLIT);
    fitness_kernel<<<fg, 256>>>(R, gidx, partial);

    sum_kernel<<<(Bn * NPn + 255) / 256, 256>>>(out);
}

// round 2
// speedup vs baseline: 1.0846x; 1.0846x over previous
#include <cuda_runtime.h>
#include <cuda_bf16.h>
#include <math.h>

#define Bn 8
#define Dn 1024
#define Gn 32
#define Kn 64
#define NPn 1024
#define NT 64        // n-rows per CTA
#define GSPLIT 4
#define GPER (Gn / GSPLIT)   // 8

// Scratch (device globals; no allocation allowed)
__device__ float g_xzT[(size_t)Bn * Dn * NPn];     // 32 MB: z transposed [b][d][n]
__device__ float g_cw[Bn * Gn * Kn];               // folded coeff*mask*weight*valid
__device__ char  g_gvalid[Bn * Gn];
__device__ float g_partial[GSPLIT * Bn * NPn];

// packed dual-fp32 FMA (Blackwell f32x2 pipe; PTX-only, ptxas won't auto-fuse)
#define FMA2(acc, m, r) \
    asm("fma.rn.f32x2 %0, %1, %2, %0;" : "+l"(acc) : "l"(m), "l"(r))

// ---------------------------------------------------------------------------
// Kernel 1: detect valid_mask storage width, build cw + gvalid (32 blocks)
// ---------------------------------------------------------------------------
__global__ void cmask_kernel(const void* __restrict__ vm,
                             const float* __restrict__ w,
                             const int* __restrict__ gc)
{
    __shared__ int mode;         // 1 = 4-byte elements, 0 = 1-byte elements
    __shared__ float cf[Kn];
    int tid = threadIdx.x;

    if (tid == 0) {
        const unsigned int* u = (const unsigned int*)vm;
        int m4 = 1;
        for (int i = 0; i < 16; ++i) {
            unsigned int v = u[i];
            if (v != 0u && v != 1u && v != 0x3F800000u) m4 = 0;
        }
        mode = m4;
    }
    if (tid < Kn) {
        cf[tid] = (float)pow(1.0e6, (double)tid / 63.0);
    }
    __syncthreads();

    int stride = blockDim.x * gridDim.x;
    for (int i = blockIdx.x * blockDim.x + tid; i < Bn * Gn * Kn; i += stride) {
        int b = i / (Gn * Kn);
        int g = (i / Kn) % Gn;
        int k = i % Kn;
        bool m;
        if (mode) m = (((const unsigned int*)vm)[i] != 0u);
        else      m = (((const unsigned char*)vm)[i] != 0);
        float wv = (g < gc[b]) ? w[b * Gn + g] : 0.0f;
        g_cw[i] = m ? cf[k] * wv : 0.0f;
    }
    for (int i = blockIdx.x * blockDim.x + tid; i < Bn * Gn; i += stride) {
        int b = i / Gn, g = i % Gn;
        g_gvalid[i] = (g < gc[b]) ? 1 : 0;
    }
}

// ---------------------------------------------------------------------------
// Kernel 2: xzT[b][d][n] = x[b][n][d] - xopt[b][d]  (tiled transpose)
// ---------------------------------------------------------------------------
__global__ void zt_kernel(const float* __restrict__ x,
                          const float* __restrict__ xopt)
{
    __shared__ float t[32][33];
    int b  = blockIdx.z;
    int n0 = blockIdx.x * 32;
    int d0 = blockIdx.y * 32;
    int tx = threadIdx.x, ty = threadIdx.y;

    #pragma unroll
    for (int j = ty; j < 32; j += 8) {
        int n = n0 + j, d = d0 + tx;
        t[j][tx] = x[((size_t)b * NPn + n) * Dn + d] - xopt[b * Dn + d];
    }
    __syncthreads();
    #pragma unroll
    for (int j = ty; j < 32; j += 8) {
        int d = d0 + j, n = n0 + tx;
        g_xzT[((size_t)b * Dn + d) * NPn + n] = t[tx][j];
    }
}

// ---------------------------------------------------------------------------
// Kernel 3: main fitness kernel.
// Grid: (Bn * NPn/NT, GSPLIT), block 256.
// Chunk p handles groups g = p, p+GSPLIT, p+2*GSPLIT, ... (interleaved for
// load balance; valid groups are a prefix so break stays monotone).
// Thread tile: 2 n x 8 l via packed f32x2 FMA (8 FFMA2 / k / thread).
//   nt = tid & 31  -> n pair (2*nt, 2*nt+1)
//   lt = tid >> 5  -> l range [lt*8, lt*8+8)   (constant per warp ->
//                     R reads are warp-broadcast LDS.128)
// ---------------------------------------------------------------------------
__global__ __launch_bounds__(256) void fitness_kernel(
    const float* __restrict__ R,
    const int*   __restrict__ gidx,
    float*       __restrict__ partial)
{
    __shared__ float Rs[Kn * Kn];       // 16 KB
    __shared__ float zs[Kn * NT];       // 16 KB, [k][n]
    __shared__ float cws[Kn];
    __shared__ int   idxs[Kn];
    __shared__ float fit_s[NT];

    int tid   = threadIdx.x;
    int b     = blockIdx.x >> 4;
    int n0    = (blockIdx.x & 15) * NT;
    int chunk = blockIdx.y;
    int nt    = tid & 31;
    int lt    = tid >> 5;

    for (int i = tid; i < Kn * Kn; i += 256) Rs[i] = R[i];
    if (tid < NT) fit_s[tid] = 0.0f;

    float fa0 = 0.0f, fa1 = 0.0f;
    __syncthreads();

    for (int gi = 0; gi < GPER; ++gi) {
        int g = chunk + gi * GSPLIT;
        if (!g_gvalid[b * Gn + g]) break;   // valid groups are a prefix
        __syncthreads();                    // prior compute done before rewrite
        if (tid < Kn) {
            idxs[tid] = gidx[(b * Gn + g) * Kn + tid];
            cws[tid]  = g_cw[(b * Gn + g) * Kn + tid];
        }
        __syncthreads();

        // Coalesced gather: 64 columns of xzT, each 64 consecutive n (float4)
        #pragma unroll
        for (int p = 0; p < 4; ++p) {
            int k   = p * 16 + (tid >> 4);
            int col = idxs[k];
            const float4* src =
                (const float4*)&g_xzT[((size_t)(b * Dn + col)) * NPn + n0] + (tid & 15);
            *((float4*)&zs[k * NT] + (tid & 15)) = *src;
        }
        __syncthreads();

        float cw_r[8];
        #pragma unroll
        for (int j = 0; j < 8; ++j) cw_r[j] = cws[lt * 8 + j];

        unsigned long long accE[4], accO[4];
        #pragma unroll
        for (int i = 0; i < 4; ++i) { accE[i] = 0ull; accO[i] = 0ull; }

        #pragma unroll 8
        for (int k = 0; k < Kn; ++k) {
            float2 z2 = *(const float2*)&zs[k * NT + nt * 2];
            unsigned long long zx2, zy2;
            asm("mov.b64 %0, {%1, %1};" : "=l"(zx2) : "f"(z2.x));
            asm("mov.b64 %0, {%1, %1};" : "=l"(zy2) : "f"(z2.y));
            const ulonglong2* rp = (const ulonglong2*)&Rs[k * Kn + lt * 8];
            ulonglong2 ra = rp[0];       // l = lt*8 .. +3
            ulonglong2 rb = rp[1];       // l = lt*8+4 .. +7
            FMA2(accE[0], zx2, ra.x);  FMA2(accE[1], zx2, ra.y);
            FMA2(accE[2], zx2, rb.x);  FMA2(accE[3], zx2, rb.y);
            FMA2(accO[0], zy2, ra.x);  FMA2(accO[1], zy2, ra.y);
            FMA2(accO[2], zy2, rb.x);  FMA2(accO[3], zy2, rb.y);
        }

        float s0 = 0.0f, s1 = 0.0f;
        #pragma unroll
        for (int j = 0; j < 4; ++j) {
            float e0 = __uint_as_float((unsigned int)(accE[j] & 0xFFFFFFFFull));
            float e1 = __uint_as_float((unsigned int)(accE[j] >> 32));
            float o0 = __uint_as_float((unsigned int)(accO[j] & 0xFFFFFFFFull));
            float o1 = __uint_as_float((unsigned int)(accO[j] >> 32));
            s0 += cw_r[2 * j] * e0 * e0 + cw_r[2 * j + 1] * e1 * e1;
            s1 += cw_r[2 * j] * o0 * o0 + cw_r[2 * j + 1] * o1 * o1;
        }
        fa0 += s0;
        fa1 += s1;
    }

    // Reduce the 8 l-chunks (one per warp) per n via shared atomics (512 total)
    atomicAdd(&fit_s[nt * 2],     fa0);
    atomicAdd(&fit_s[nt * 2 + 1], fa1);
    __syncthreads();
    if (tid < NT) {
        partial[(size_t)blockIdx.y * (Bn * NPn) + b * NPn + n0 + tid] = fit_s[tid];
    }
}

// ---------------------------------------------------------------------------
// Kernel 4: sum the GSPLIT partials
// ---------------------------------------------------------------------------
__global__ void sum_kernel(float* __restrict__ out)
{
    int i = blockIdx.x * blockDim.x + threadIdx.x;
    if (i < Bn * NPn) {
        float s = 0.0f;
        #pragma unroll
        for (int p = 0; p < GSPLIT; ++p) s += g_partial[p * (Bn * NPn) + i];
        out[i] = s;
    }
}

// ---------------------------------------------------------------------------
// kernel_launch
// Inputs (metadata order): x, weights, xopt, R, group_indices, valid_mask,
//                          group_counts
// ---------------------------------------------------------------------------
extern "C" void kernel_launch(void* const* d_in, const int* in_sizes, int n_in,
                              void* d_out, int out_size)
{
    const float* x      = (const float*)d_in[0];
    const float* w      = (const float*)d_in[1];
    const float* xopt   = (const float*)d_in[2];
    const float* R      = (const float*)d_in[3];
    const int*   gidx   = (const int*)d_in[4];
    const void*  vmask  = (const void*)d_in[5];
    const int*   gc     = (const int*)d_in[6];
    float*       out    = (float*)d_out;

    float* partial;
    cudaGetSymbolAddress((void**)&partial, g_partial);

    cmask_kernel<<<32, 256>>>(vmask, w, gc);

    dim3 tg(NPn / 32, Dn / 32, Bn);
    zt_kernel<<<tg, dim3(32, 8)>>>(x, xopt);

    dim3 fg(Bn * (NPn / NT), GSPLIT);
    fitness_kernel<<<fg, 256>>>(R, gidx, partial);

    sum_kernel<<<(Bn * NPn + 255) / 256, 256>>>(out);
}